// round 10
// baseline (speedup 1.0000x reference)
#include <cuda_runtime.h>

// deblurNet: out = x @ W.T with W complex DIAGONAL:
//   out[b,i] = (xr + j*xi)[b,i] * W[i,i]
//
// R9 post-mortem: latency-bound, occ capped ~48% by grid size, block sync
// serializes on the scattered diag gather. This round: barrier-free
// warp-local kernel. Warp owns 32 cols x 2 batches; lane l gathers diag
// col0+l and redistributes via 4 shfl.sync (no smem, no __syncthreads).
// 2 complex/thread -> 9216 warps (1152 blocks) -> ~2x occupancy.

#define TOT   589824   // B*N complex elements (64 * 9216)
#define NDIM  9216     // N = 96*96
#define DSTR  9217     // diagonal stride in dense [N,N] f32 storage
#define BATCH 64
#define CWARPS (NDIM / 32)          // 288 column-warps
#define BGRPS  (BATCH / 2)          // 32 batch groups (2 rows per warp)
#define NWARPS (CWARPS * BGRPS)     // 9216 warps total

__global__ void __launch_bounds__(256)
deblur_warp(const float* __restrict__ xr,
            const float* __restrict__ xi,
            const float* __restrict__ wr,
            const float* __restrict__ wi,
            float* __restrict__ out,
            int mode) {
    const int tid  = threadIdx.x;
    const int lane = tid & 31;
    const int W    = (blockIdx.x * blockDim.x + tid) >> 5;  // 0 .. 9215
    const int colwarp = W % CWARPS;        // consecutive warps -> adjacent cols
    const int bg      = W / CWARPS;        // 0 .. 31
    const int col0    = colwarp * 32;

    // Each lane gathers ONE diagonal complex entry (its column).
    // Max offset (NDIM-1)*DSTR = N^2-1: in-bounds. L2-resident after the
    // first batch group touches these sectors.
    const long long d = (long long)(col0 + lane) * DSTR;
    const float mywr = __ldg(wr + d);
    const float mywi = __ldg(wi + d);

    // Thread (b, cg): b = lane>>4 (2 batches), cg = lane&15 (2 cols each).
    const int cg = lane & 15;
    const int b  = lane >> 4;
    const int row = bg * 2 + b;
    const int i   = col0 + cg * 2;
    const int idx = row * NDIM + i;        // max TOT-2: in-bounds

    // Independent x loads issue before the shfl dependency resolves.
    const float2 ar = *reinterpret_cast<const float2*>(xr + idx);
    const float2 ai = *reinterpret_cast<const float2*>(xi + idx);

    // Redistribute diag: columns 2cg, 2cg+1 live in lanes 2cg, 2cg+1.
    const float w0r = __shfl_sync(0xffffffffu, mywr, cg * 2);
    const float w0i = __shfl_sync(0xffffffffu, mywi, cg * 2);
    const float w1r = __shfl_sync(0xffffffffu, mywr, cg * 2 + 1);
    const float w1i = __shfl_sync(0xffffffffu, mywi, cg * 2 + 1);

    const float o0r = fmaf(ar.x, w0r, -ai.x * w0i), o0i = fmaf(ar.x, w0i, ai.x * w0r);
    const float o1r = fmaf(ar.y, w1r, -ai.y * w1i), o1i = fmaf(ar.y, w1i, ai.y * w1r);

    if (mode == 1) {
        // Interleaved re/im (f32 view of complex64): 2 complex = one float4.
        // idx is even -> out + 2*idx is 16B-aligned.
        *reinterpret_cast<float4*>(out + 2 * idx) = make_float4(o0r, o0i, o1r, o1i);
    } else {
        // Real part only: TOT floats.
        *reinterpret_cast<float2*>(out + idx) = make_float2(o0r, o1r);
    }
}

extern "C" void kernel_launch(void* const* d_in, const int* in_sizes, int n_in,
                              void* d_out, int out_size) {
    if (n_in < 4) return;

    // Inputs are f32 at reported element counts (confirmed R6-R9 passes).
    // Smaller-size pair = x (B*N), larger pair = W (N*N); real before imag.
    long long smin = -1;
    for (int k = 0; k < 4; ++k) {
        long long s = (long long)in_sizes[k];
        if (smin < 0 || s < smin) smin = s;
    }
    const float* xs[2] = {nullptr, nullptr};
    const float* ws[2] = {nullptr, nullptr};
    int nx = 0, nw = 0;
    for (int k = 0; k < 4; ++k) {
        if ((long long)in_sizes[k] == smin && nx < 2) xs[nx++] = (const float*)d_in[k];
        else if (nw < 2)                              ws[nw++] = (const float*)d_in[k];
    }
    if (nx < 2 || nw < 2) return;

    // Output mode strictly bounded by out_size (4-byte elements).
    const int mode = ((long long)out_size >= 2LL * TOT) ? 1 : 0;

    const int threads = 256;
    const int blocks  = (NWARPS * 32) / threads;   // 1152
    deblur_warp<<<blocks, threads>>>(xs[0], xs[1], ws[0], ws[1],
                                     (float*)d_out, mode);
}

// round 11
// speedup vs baseline: 1.2947x; 1.2947x over previous
#include <cuda_runtime.h>

// deblurNet: out = x @ W.T with W complex DIAGONAL:
//   out[b,i] = (xr + j*xi)[b,i] * W[i,i]
//
// R10 post-mortem: wallclock tracks SCATTERED-LOAD COUNT across all rounds
// (1.18M->12.7us, 590K->8.6us, 295K->6.9us, 74K->6.7us), not occupancy.
// R11: block = 16 cols x ALL 64 batches -> each diagonal column gathered
// exactly once chip-wide (18,432 scattered loads). Keep the winning R9
// grid shape (576 x 256). New: prefetch x into registers BEFORE the
// __syncthreads so the barrier hides the gather latency under the x loads.

#define TOT   589824   // B*N complex elements (64 * 9216)
#define NDIM  9216     // N = 96*96
#define DSTR  9217     // diagonal stride in dense [N,N] f32 storage
#define BATCH 64
#define TC    16               // columns per block (gathered ONCE)
#define NBLK  (NDIM / TC)      // 576 blocks

__global__ void __launch_bounds__(256)
deblur_tiled2(const float* __restrict__ xr,
              const float* __restrict__ xi,
              const float* __restrict__ wr,
              const float* __restrict__ wi,
              float* __restrict__ out,
              int mode) {
    __shared__ float2 s_diag[TC];

    const int tid  = threadIdx.x;
    const int col0 = blockIdx.x * TC;

    // Phase 1a: issue the diagonal gather (32 scattered LDG.32 per block).
    // Max offset (NDIM-1)*DSTR = N^2-1: in-bounds.
    if (tid < TC) {
        const long long d = (long long)(col0 + tid) * DSTR;
        s_diag[tid] = make_float2(__ldg(wr + d), __ldg(wi + d));
    }

    // Phase 1b: prefetch x BEFORE the barrier -- independent of the gather,
    // so the BAR release waits on max(gather, x-load), not their sum.
    const int cg = tid & 3;                // 0..3  -> cols col0 + cg*4 .. +3
    const int b  = tid >> 2;               // 0..63 -> batch row
    const int i   = col0 + cg * 4;
    const int idx = b * NDIM + i;          // max TOT-4: in-bounds
    const float4 ar = *reinterpret_cast<const float4*>(xr + idx);
    const float4 ai = *reinterpret_cast<const float4*>(xi + idx);

    __syncthreads();

    // Phase 2: broadcast smem reads (all 64 b-threads share a cg -> N=1).
    const float2 w0 = s_diag[cg * 4 + 0];
    const float2 w1 = s_diag[cg * 4 + 1];
    const float2 w2 = s_diag[cg * 4 + 2];
    const float2 w3 = s_diag[cg * 4 + 3];

    const float o0r = fmaf(ar.x, w0.x, -ai.x * w0.y), o0i = fmaf(ar.x, w0.y, ai.x * w0.x);
    const float o1r = fmaf(ar.y, w1.x, -ai.y * w1.y), o1i = fmaf(ar.y, w1.y, ai.y * w1.x);
    const float o2r = fmaf(ar.z, w2.x, -ai.z * w2.y), o2i = fmaf(ar.z, w2.y, ai.z * w2.x);
    const float o3r = fmaf(ar.w, w3.x, -ai.w * w3.y), o3i = fmaf(ar.w, w3.y, ai.w * w3.x);

    if (mode == 1) {
        // Interleaved re/im (f32 view of complex64): 2*TOT floats.
        float4* o = reinterpret_cast<float4*>(out) + (idx >> 1);
        o[0] = make_float4(o0r, o0i, o1r, o1i);
        o[1] = make_float4(o2r, o2i, o3r, o3i);
    } else {
        // Real part only: TOT floats.
        *reinterpret_cast<float4*>(out + idx) = make_float4(o0r, o1r, o2r, o3r);
    }
}

extern "C" void kernel_launch(void* const* d_in, const int* in_sizes, int n_in,
                              void* d_out, int out_size) {
    if (n_in < 4) return;

    // Inputs are f32 at reported element counts (confirmed R6-R10 passes).
    // Smaller-size pair = x (B*N), larger pair = W (N*N); real before imag.
    long long smin = -1;
    for (int k = 0; k < 4; ++k) {
        long long s = (long long)in_sizes[k];
        if (smin < 0 || s < smin) smin = s;
    }
    const float* xs[2] = {nullptr, nullptr};
    const float* ws[2] = {nullptr, nullptr};
    int nx = 0, nw = 0;
    for (int k = 0; k < 4; ++k) {
        if ((long long)in_sizes[k] == smin && nx < 2) xs[nx++] = (const float*)d_in[k];
        else if (nw < 2)                              ws[nw++] = (const float*)d_in[k];
    }
    if (nx < 2 || nw < 2) return;

    // Output mode strictly bounded by out_size (4-byte elements).
    const int mode = ((long long)out_size >= 2LL * TOT) ? 1 : 0;

    deblur_tiled2<<<NBLK, 256>>>(xs[0], xs[1], ws[0], ws[1],
                                 (float*)d_out, mode);   // 576 blocks
}